// round 7
// baseline (speedup 1.0000x reference)
#include <cuda_runtime.h>
#include <cstdint>

#define B_ROWS   2000000u
#define F_COLS   21u
#define NUM_CLASSES 7

#define NBLOCKS  740              // = 148 SMs * 5 blocks: one perfectly balanced wave
#define NTHREADS 256

// Rows handed out in quads (4 rows = 84 elems = 336 B, keeps tiles 16B-aligned).
#define TOTAL_QUADS 500000u       // 2,000,000 / 4
#define QUADS_LO    675u          // 740*675 + 500 = 500000
#define BIG_BLOCKS  500u          // first 500 blocks get 676 quads

#define TILE_ROWS  64u
#define TILE_ELEMS (TILE_ROWS * F_COLS)   // 1344
#define TILE_BYTES (TILE_ELEMS * 4u)      // 5376 per array
#define DEPTH      4

__device__ double        g_part_wd[NBLOCKS];
__device__ double        g_part_pen[NBLOCKS];
__device__ unsigned int  g_done_count = 0;

// ---------- PTX helpers ----------
__device__ __forceinline__ unsigned smem_u32(const void* p) {
    return (unsigned)__cvta_generic_to_shared(p);
}
__device__ __forceinline__ void mbar_init(unsigned a, unsigned cnt) {
    asm volatile("mbarrier.init.shared.b64 [%0], %1;" :: "r"(a), "r"(cnt) : "memory");
}
__device__ __forceinline__ void mbar_expect_tx(unsigned a, unsigned bytes) {
    asm volatile("mbarrier.arrive.expect_tx.shared.b64 _, [%0], %1;"
                 :: "r"(a), "r"(bytes) : "memory");
}
__device__ __forceinline__ void mbar_arrive(unsigned a) {
    asm volatile("mbarrier.arrive.release.cta.shared.b64 _, [%0];" :: "r"(a) : "memory");
}
__device__ __forceinline__ void bulk_g2s(unsigned dst, const void* src, unsigned bytes, unsigned mbar) {
    asm volatile("cp.async.bulk.shared::cluster.global.mbarrier::complete_tx::bytes [%0], [%1], %2, [%3];"
                 :: "r"(dst), "l"(src), "r"(bytes), "r"(mbar) : "memory");
}
__device__ __forceinline__ void mbar_wait(unsigned a, unsigned parity) {
    asm volatile(
        "{\n\t"
        ".reg .pred P;\n"
        "W%=:\n\t"
        "mbarrier.try_wait.parity.acquire.cta.shared::cta.b64 P, [%0], %1, 0x989680;\n\t"
        "@P bra D%=;\n\t"
        "bra W%=;\n"
        "D%=:\n\t"
        "}" :: "r"(a), "r"(parity) : "memory");
}

__global__ __launch_bounds__(NTHREADS, 5)
void wmse_tma_kernel(const float* __restrict__ x,
                     const int*   __restrict__ t,
                     const float* __restrict__ w,
                     float*       __restrict__ out)
{
    __shared__ alignas(128) float s_x[DEPTH][TILE_ELEMS];
    __shared__ alignas(128) int   s_t[DEPTH][TILE_ELEMS];
    __shared__ alignas(16)  unsigned long long s_full[DEPTH];
    __shared__ alignas(16)  unsigned long long s_empty[DEPTH];
    __shared__ float  s_wtab[NUM_CLASSES];
    __shared__ float  s_rwd[NTHREADS / 32];
    __shared__ float  s_rpen[NTHREADS / 32];
    __shared__ bool   s_is_last;

    const unsigned tid = threadIdx.x;
    const unsigned b   = blockIdx.x;

    const unsigned nquads    = (b < BIG_BLOCKS) ? (QUADS_LO + 1u) : QUADS_LO;
    const unsigned startq    = QUADS_LO * b + min(b, BIG_BLOCKS);
    const unsigned rows      = nquads * 4u;
    const unsigned elem_base = startq * 84u;
    const unsigned ntiles    = (rows + TILE_ROWS - 1u) / TILE_ROWS;   // 43

    if (tid < NUM_CLASSES) s_wtab[tid] = w[tid];
    if (tid == 0) {
        #pragma unroll
        for (int i = 0; i < DEPTH; ++i) {
            mbar_init(smem_u32(&s_full[i]), 1u);
            mbar_init(smem_u32(&s_empty[i]), NTHREADS);
        }
    }
    __syncthreads();

    // Prime the pipeline
    if (tid == 0) {
        #pragma unroll
        for (unsigned i = 0; i < DEPTH; ++i) {
            const unsigned trows = min(TILE_ROWS, rows - i * TILE_ROWS);
            const unsigned bytes = trows * F_COLS * 4u;
            const unsigned mb    = smem_u32(&s_full[i]);
            mbar_expect_tx(mb, 2u * bytes);
            bulk_g2s(smem_u32(&s_x[i][0]), x + elem_base + i * TILE_ELEMS, bytes, mb);
            bulk_g2s(smem_u32(&s_t[i][0]), t + elem_base + i * TILE_ELEMS, bytes, mb);
        }
    }

    // Per-thread slot constants: tile length ≡ 0 (mod 21) -> phases fixed across tiles.
    const unsigned e0 = tid * 4u;
    const unsigned e1 = (tid + NTHREADS) * 4u;
    const unsigned r0 = e0 / F_COLS,       r1 = e1 / F_COLS;
    const unsigned c0 = e0 - r0 * F_COLS,  c1 = e1 - r1 * F_COLS;
    const bool     bd0 = (c0 >= 18u),      bd1 = (c1 >= 18u);
    const unsigned sp0 = F_COLS - c0,      sp1 = F_COLS - c1;
    const unsigned rb0 = r0 * F_COLS,      rb1 = r1 * F_COLS;   // row base elem idx

    float accw = 0.0f, accp = 0.0f;

    for (unsigned i = 0; i < ntiles; ++i) {
        const unsigned stg    = i & (DEPTH - 1u);
        const unsigned parity = (i / DEPTH) & 1u;
        mbar_wait(smem_u32(&s_full[stg]), parity);

        const unsigned trows = min(TILE_ROWS, rows - i * TILE_ROWS);
        const unsigned nvec  = trows * F_COLS / 4u;

        // Per-row penalty: one thread per row, straight from smem.
        if (tid < trows) {
            const float vv = (float)s_t[stg][tid * F_COLS + 1u];
            if (vv > 1000.0f) {
                const float e = vv - 1000.0f;
                accp = fmaf(e, e, accp);
            } else if (vv < 0.0f) {
                accp = fmaf(vv, vv, accp);
            }
        }

        if (tid < nvec) {       // slot 0 (tid < 336 always true except short last tile)
            const float4 xv = *reinterpret_cast<const float4*>(&s_x[stg][e0]);
            const int4   tv = *reinterpret_cast<const int4*>(&s_t[stg][e0]);
            const unsigned cls = (unsigned)s_t[stg][rb0 + 2u];
            const float w0 = s_wtab[cls / 100u - 1u];
            const float d0 = xv.x - (float)tv.x;
            const float d1 = xv.y - (float)tv.y;
            const float d2 = xv.z - (float)tv.z;
            const float d3 = xv.w - (float)tv.w;
            const float q0 = d0*d0, q1 = d1*d1, q2 = d2*d2, q3 = d3*d3;
            const float q  = (q0 + q1) + (q2 + q3);
            accw = fmaf(w0, q, accw);
            if (bd0) {
                const unsigned cls1 = (unsigned)s_t[stg][rb0 + F_COLS + 2u];
                const float w1 = s_wtab[cls1 / 100u - 1u];
                float qhi = q3;
                if (sp0 <= 2u) qhi += q2;
                if (sp0 <= 1u) qhi += q1;
                accw = fmaf(w1 - w0, qhi, accw);
            }
        }
        if (tid + NTHREADS < nvec) {   // slot 1
            const float4 xv = *reinterpret_cast<const float4*>(&s_x[stg][e1]);
            const int4   tv = *reinterpret_cast<const int4*>(&s_t[stg][e1]);
            const unsigned cls = (unsigned)s_t[stg][rb1 + 2u];
            const float w0 = s_wtab[cls / 100u - 1u];
            const float d0 = xv.x - (float)tv.x;
            const float d1 = xv.y - (float)tv.y;
            const float d2 = xv.z - (float)tv.z;
            const float d3 = xv.w - (float)tv.w;
            const float q0 = d0*d0, q1 = d1*d1, q2 = d2*d2, q3 = d3*d3;
            const float q  = (q0 + q1) + (q2 + q3);
            accw = fmaf(w0, q, accw);
            if (bd1) {
                const unsigned cls1 = (unsigned)s_t[stg][rb1 + F_COLS + 2u];
                const float w1 = s_wtab[cls1 / 100u - 1u];
                float qhi = q3;
                if (sp1 <= 2u) qhi += q2;
                if (sp1 <= 1u) qhi += q1;
                accw = fmaf(w1 - w0, qhi, accw);
            }
        }

        // Done with this stage.
        mbar_arrive(smem_u32(&s_empty[stg]));

        // Producer: refill this stage once all 256 consumers have arrived.
        const unsigned nx = i + DEPTH;
        if (tid == 0 && nx < ntiles) {
            mbar_wait(smem_u32(&s_empty[stg]), parity);
            const unsigned trN   = min(TILE_ROWS, rows - nx * TILE_ROWS);
            const unsigned bytes = trN * F_COLS * 4u;
            const unsigned mb    = smem_u32(&s_full[stg]);
            mbar_expect_tx(mb, 2u * bytes);
            bulk_g2s(smem_u32(&s_x[stg][0]), x + elem_base + nx * TILE_ELEMS, bytes, mb);
            bulk_g2s(smem_u32(&s_t[stg][0]), t + elem_base + nx * TILE_ELEMS, bytes, mb);
        }
    }

    // ---- block reduction ----
    #pragma unroll
    for (int o = 16; o > 0; o >>= 1) {
        accw += __shfl_xor_sync(0xffffffffu, accw, o);
        accp += __shfl_xor_sync(0xffffffffu, accp, o);
    }
    const int warp = tid >> 5;
    const int lane = tid & 31;
    if (lane == 0) { s_rwd[warp] = accw; s_rpen[warp] = accp; }
    __syncthreads();

    if (tid == 0) {
        double dw = 0.0, dp = 0.0;
        #pragma unroll
        for (int i = 0; i < NTHREADS / 32; ++i) { dw += (double)s_rwd[i]; dp += (double)s_rpen[i]; }
        g_part_wd[b]  = dw;
        g_part_pen[b] = dp;
        __threadfence();
        const unsigned prev = atomicAdd(&g_done_count, 1u);
        s_is_last = (prev == (unsigned)(gridDim.x - 1));
    }
    __syncthreads();

    if (s_is_last) {
        __threadfence();
        double dw = 0.0, dp = 0.0;
        for (unsigned i = tid; i < NBLOCKS; i += NTHREADS) {
            dw += g_part_wd[i];
            dp += g_part_pen[i];
        }
        #pragma unroll
        for (int o = 16; o > 0; o >>= 1) {
            dw += __shfl_xor_sync(0xffffffffu, dw, o);
            dp += __shfl_xor_sync(0xffffffffu, dp, o);
        }
        __shared__ double f_wd[NTHREADS / 32];
        __shared__ double f_pen[NTHREADS / 32];
        if (lane == 0) { f_wd[warp] = dw; f_pen[warp] = dp; }
        __syncthreads();
        if (tid == 0) {
            double tw = 0.0, tp = 0.0;
            #pragma unroll
            for (int i = 0; i < NTHREADS / 32; ++i) { tw += f_wd[i]; tp += f_pen[i]; }
            const double mean_wd = tw / (double)((unsigned long long)B_ROWS * F_COLS);
            out[0] = (float)(mean_wd + tp);
            g_done_count = 0;   // reset for next graph replay
        }
    }
}

extern "C" void kernel_launch(void* const* d_in, const int* in_sizes, int n_in,
                              void* d_out, int out_size)
{
    const float* x = nullptr;
    const int*   t = nullptr;
    const float* w = nullptr;
    int big_seen = 0;
    for (int i = 0; i < n_in; ++i) {
        if (in_sizes[i] == NUM_CLASSES) {
            w = (const float*)d_in[i];
        } else {
            if (big_seen == 0) x = (const float*)d_in[i];
            else               t = (const int*)d_in[i];
            big_seen++;
        }
    }
    wmse_tma_kernel<<<NBLOCKS, NTHREADS>>>(x, t, w, (float*)d_out);
}

// round 11
// speedup vs baseline: 1.0328x; 1.0328x over previous
#include <cuda_runtime.h>
#include <cstdint>

#define B_ROWS   2000000u
#define F_COLS   21u
#define NUM_CLASSES 7

#define NBLOCKS  296              // = 148 SMs * 2 blocks: one wave
#define NTHREADS 512
#define NWARPS   (NTHREADS / 32)

// Rows handed out in quads (4 rows = 84 elems = 336 B -> 16B-aligned tile starts).
#define TOTAL_QUADS 500000u       // 2,000,000 / 4
#define QUADS_LO    1689u         // 296*1689 + 56 = 500000
#define BIG_BLOCKS  56u           // first 56 blocks get 1690 quads

#define TILE_ROWS  128u
#define TILE_ELEMS (TILE_ROWS * F_COLS)   // 2688 (= 21*128, ≡ 0 mod 21)
#define TILE_BYTES (TILE_ELEMS * 4u)      // 10752 per array per tile
#define DEPTH      4

__device__ double        g_part_wd[NBLOCKS];
__device__ double        g_part_pen[NBLOCKS];
__device__ unsigned int  g_done_count = 0;

// ---------- PTX helpers ----------
__device__ __forceinline__ unsigned smem_u32(const void* p) {
    return (unsigned)__cvta_generic_to_shared(p);
}
__device__ __forceinline__ void mbar_init(unsigned a, unsigned cnt) {
    asm volatile("mbarrier.init.shared.b64 [%0], %1;" :: "r"(a), "r"(cnt) : "memory");
}
__device__ __forceinline__ void mbar_expect_tx(unsigned a, unsigned bytes) {
    asm volatile("mbarrier.arrive.expect_tx.shared.b64 _, [%0], %1;"
                 :: "r"(a), "r"(bytes) : "memory");
}
__device__ __forceinline__ void bulk_g2s(unsigned dst, const void* src, unsigned bytes, unsigned mbar) {
    asm volatile("cp.async.bulk.shared::cluster.global.mbarrier::complete_tx::bytes [%0], [%1], %2, [%3];"
                 :: "r"(dst), "l"(src), "r"(bytes), "r"(mbar) : "memory");
}
__device__ __forceinline__ void mbar_wait(unsigned a, unsigned parity) {
    asm volatile(
        "{\n\t"
        ".reg .pred P;\n"
        "W%=:\n\t"
        "mbarrier.try_wait.parity.acquire.cta.shared::cta.b64 P, [%0], %1, 0x989680;\n\t"
        "@P bra D%=;\n\t"
        "bra W%=;\n"
        "D%=:\n\t"
        "}" :: "r"(a), "r"(parity) : "memory");
}

struct Smem {
    alignas(128) float x[DEPTH][TILE_ELEMS];
    alignas(128) int   t[DEPTH][TILE_ELEMS];
    alignas(16)  unsigned long long mbar[DEPTH];
    float  wrow[TILE_ROWS];
    float  wtab[NUM_CLASSES];
    float  rwd[NWARPS];
    float  rpen[NWARPS];
    double fwd[NWARPS];
    double fpen[NWARPS];
    bool   is_last;
};

__global__ __launch_bounds__(NTHREADS, 2)
void wmse_tma_kernel(const float* __restrict__ x,
                     const int*   __restrict__ t,
                     const float* __restrict__ w,
                     float*       __restrict__ out)
{
    extern __shared__ char smem_raw[];
    Smem* s = reinterpret_cast<Smem*>(smem_raw);

    const unsigned tid = threadIdx.x;
    const unsigned b   = blockIdx.x;

    const unsigned nquads    = (b < BIG_BLOCKS) ? (QUADS_LO + 1u) : QUADS_LO;
    const unsigned startq    = QUADS_LO * b + min(b, BIG_BLOCKS);
    const unsigned rows      = nquads * 4u;                        // 6756 / 6760
    const unsigned elem_base = startq * 84u;
    const unsigned ntiles    = (rows + TILE_ROWS - 1u) / TILE_ROWS; // 53

    if (tid < NUM_CLASSES) s->wtab[tid] = w[tid];
    if (tid == 0) {
        #pragma unroll
        for (int i = 0; i < DEPTH; ++i)
            mbar_init(smem_u32(&s->mbar[i]), 1u);
    }
    __syncthreads();

    // Prime the pipeline
    if (tid == 0) {
        #pragma unroll
        for (unsigned i = 0; i < DEPTH; ++i) {
            const unsigned trows = min(TILE_ROWS, rows - i * TILE_ROWS);
            const unsigned bytes = trows * F_COLS * 4u;
            const unsigned mb    = smem_u32(&s->mbar[i]);
            mbar_expect_tx(mb, 2u * bytes);
            bulk_g2s(smem_u32(&s->x[i][0]), x + elem_base + i * TILE_ELEMS, bytes, mb);
            bulk_g2s(smem_u32(&s->t[i][0]), t + elem_base + i * TILE_ELEMS, bytes, mb);
        }
    }

    // Per-thread slot constants: tile length ≡ 0 (mod 21) -> phases fixed across tiles.
    const unsigned e0 = tid * 4u;
    const unsigned e1 = (tid + NTHREADS) * 4u;
    const unsigned r0 = e0 / F_COLS,       r1 = e1 / F_COLS;
    const unsigned c0 = e0 - r0 * F_COLS,  c1 = e1 - r1 * F_COLS;
    const bool     bd0 = (c0 >= 18u),      bd1 = (c1 >= 18u);
    const unsigned sp0 = F_COLS - c0,      sp1 = F_COLS - c1;

    float accw = 0.0f, accp = 0.0f;

    for (unsigned i = 0; i < ntiles; ++i) {
        const unsigned stg = i & (DEPTH - 1u);
        mbar_wait(smem_u32(&s->mbar[stg]), (i / DEPTH) & 1u);

        const unsigned trows = min(TILE_ROWS, rows - i * TILE_ROWS);
        // Per-row work from smem: weight table + penalty, once per row.
        if (tid < trows) {
            const int cls = s->t[stg][tid * F_COLS + 2u];
            s->wrow[tid] = s->wtab[(unsigned)cls / 100u - 1u];
            const float vv = (float)s->t[stg][tid * F_COLS + 1u];
            if (vv > 1000.0f) {
                const float e = vv - 1000.0f;
                accp = fmaf(e, e, accp);
            } else if (vv < 0.0f) {
                accp = fmaf(vv, vv, accp);
            }
        }
        __syncthreads();

        const unsigned nvec = trows * F_COLS / 4u;   // trows multiple of 4 -> exact

        if (tid < nvec) {
            const float4 xv = *reinterpret_cast<const float4*>(&s->x[stg][e0]);
            const int4   tv = *reinterpret_cast<const int4*>(&s->t[stg][e0]);
            const float w0 = s->wrow[r0];
            const float d0 = xv.x - (float)tv.x;
            const float d1 = xv.y - (float)tv.y;
            const float d2 = xv.z - (float)tv.z;
            const float d3 = xv.w - (float)tv.w;
            const float q0 = d0*d0, q1 = d1*d1, q2 = d2*d2, q3 = d3*d3;
            const float q  = (q0 + q1) + (q2 + q3);
            accw = fmaf(w0, q, accw);
            if (bd0) {
                const float w1 = s->wrow[r0 + 1u];
                float qhi = q3;
                if (sp0 <= 2u) qhi += q2;
                if (sp0 <= 1u) qhi += q1;
                accw = fmaf(w1 - w0, qhi, accw);
            }
        }
        if (tid + NTHREADS < nvec) {
            const float4 xv = *reinterpret_cast<const float4*>(&s->x[stg][e1]);
            const int4   tv = *reinterpret_cast<const int4*>(&s->t[stg][e1]);
            const float w0 = s->wrow[r1];
            const float d0 = xv.x - (float)tv.x;
            const float d1 = xv.y - (float)tv.y;
            const float d2 = xv.z - (float)tv.z;
            const float d3 = xv.w - (float)tv.w;
            const float q0 = d0*d0, q1 = d1*d1, q2 = d2*d2, q3 = d3*d3;
            const float q  = (q0 + q1) + (q2 + q3);
            accw = fmaf(w0, q, accw);
            if (bd1) {
                const float w1 = s->wrow[r1 + 1u];
                float qhi = q3;
                if (sp1 <= 2u) qhi += q2;
                if (sp1 <= 1u) qhi += q1;
                accw = fmaf(w1 - w0, qhi, accw);
            }
        }
        __syncthreads();   // stage + wrow fully consumed

        // Refill this stage with tile i+DEPTH
        const unsigned nx = i + DEPTH;
        if (tid == 0 && nx < ntiles) {
            const unsigned trN   = min(TILE_ROWS, rows - nx * TILE_ROWS);
            const unsigned bytes = trN * F_COLS * 4u;
            const unsigned mb    = smem_u32(&s->mbar[stg]);
            mbar_expect_tx(mb, 2u * bytes);
            bulk_g2s(smem_u32(&s->x[stg][0]), x + elem_base + nx * TILE_ELEMS, bytes, mb);
            bulk_g2s(smem_u32(&s->t[stg][0]), t + elem_base + nx * TILE_ELEMS, bytes, mb);
        }
    }

    // ---- block reduction ----
    #pragma unroll
    for (int o = 16; o > 0; o >>= 1) {
        accw += __shfl_xor_sync(0xffffffffu, accw, o);
        accp += __shfl_xor_sync(0xffffffffu, accp, o);
    }
    const int warp = tid >> 5;
    const int lane = tid & 31;
    if (lane == 0) { s->rwd[warp] = accw; s->rpen[warp] = accp; }
    __syncthreads();

    if (tid == 0) {
        double dw = 0.0, dp = 0.0;
        #pragma unroll
        for (int i = 0; i < NWARPS; ++i) { dw += (double)s->rwd[i]; dp += (double)s->rpen[i]; }
        g_part_wd[b]  = dw;
        g_part_pen[b] = dp;
        __threadfence();
        const unsigned prev = atomicAdd(&g_done_count, 1u);
        s->is_last = (prev == (unsigned)(gridDim.x - 1));
    }
    __syncthreads();

    if (s->is_last) {
        __threadfence();
        double dw = 0.0, dp = 0.0;
        for (unsigned i = tid; i < NBLOCKS; i += NTHREADS) {
            dw += g_part_wd[i];
            dp += g_part_pen[i];
        }
        #pragma unroll
        for (int o = 16; o > 0; o >>= 1) {
            dw += __shfl_xor_sync(0xffffffffu, dw, o);
            dp += __shfl_xor_sync(0xffffffffu, dp, o);
        }
        if (lane == 0) { s->fwd[warp] = dw; s->fpen[warp] = dp; }
        __syncthreads();
        if (tid == 0) {
            double tw = 0.0, tp = 0.0;
            #pragma unroll
            for (int i = 0; i < NWARPS; ++i) { tw += s->fwd[i]; tp += s->fpen[i]; }
            const double mean_wd = tw / (double)((unsigned long long)B_ROWS * F_COLS);
            out[0] = (float)(mean_wd + tp);
            g_done_count = 0;   // reset for next graph replay
        }
    }
}

extern "C" void kernel_launch(void* const* d_in, const int* in_sizes, int n_in,
                              void* d_out, int out_size)
{
    const float* x = nullptr;
    const int*   t = nullptr;
    const float* w = nullptr;
    int big_seen = 0;
    for (int i = 0; i < n_in; ++i) {
        if (in_sizes[i] == NUM_CLASSES) {
            w = (const float*)d_in[i];
        } else {
            if (big_seen == 0) x = (const float*)d_in[i];
            else               t = (const int*)d_in[i];
            big_seen++;
        }
    }

    static bool attr_done = false;
    if (!attr_done) {
        cudaFuncSetAttribute(wmse_tma_kernel,
                             cudaFuncAttributeMaxDynamicSharedMemorySize,
                             (int)sizeof(Smem));
        attr_done = true;
    }

    wmse_tma_kernel<<<NBLOCKS, NTHREADS, sizeof(Smem)>>>(x, t, w, (float*)d_out);
}

// round 12
// speedup vs baseline: 1.0609x; 1.0272x over previous
#include <cuda_runtime.h>
#include <cstdint>

#define B_ROWS   2000000u
#define F_COLS   21u
#define NUM_CLASSES 7

#define NBLOCKS  740              // = 148 SMs * 5 blocks: one balanced wave
#define NTHREADS 256

// Rows handed out in quads (4 rows = 84 elems = 336 B -> 16B-aligned tile starts).
#define TOTAL_QUADS 500000u       // 2,000,000 / 4
#define QUADS_LO    675u          // 740*675 + 500 = 500000
#define BIG_BLOCKS  500u          // first 500 blocks get 676 quads

#define TILE_ROWS  64u
#define TILE_ELEMS (TILE_ROWS * F_COLS)   // 1344
#define TILE_BYTES (TILE_ELEMS * 4u)      // 5376 per array
#define DEPTH      4

__device__ double        g_part_wd[NBLOCKS];
__device__ double        g_part_pen[NBLOCKS];
__device__ unsigned int  g_done_count = 0;

// ---------- PTX helpers ----------
__device__ __forceinline__ unsigned smem_u32(const void* p) {
    return (unsigned)__cvta_generic_to_shared(p);
}
__device__ __forceinline__ void mbar_init(unsigned a, unsigned cnt) {
    asm volatile("mbarrier.init.shared.b64 [%0], %1;" :: "r"(a), "r"(cnt) : "memory");
}
__device__ __forceinline__ void mbar_expect_tx(unsigned a, unsigned bytes) {
    asm volatile("mbarrier.arrive.expect_tx.shared.b64 _, [%0], %1;"
                 :: "r"(a), "r"(bytes) : "memory");
}
__device__ __forceinline__ void bulk_g2s(unsigned dst, const void* src, unsigned bytes, unsigned mbar) {
    asm volatile("cp.async.bulk.shared::cluster.global.mbarrier::complete_tx::bytes [%0], [%1], %2, [%3];"
                 :: "r"(dst), "l"(src), "r"(bytes), "r"(mbar) : "memory");
}
__device__ __forceinline__ void mbar_wait(unsigned a, unsigned parity) {
    asm volatile(
        "{\n\t"
        ".reg .pred P;\n"
        "W%=:\n\t"
        "mbarrier.try_wait.parity.acquire.cta.shared::cta.b64 P, [%0], %1, 0x989680;\n\t"
        "@P bra D%=;\n\t"
        "bra W%=;\n"
        "D%=:\n\t"
        "}" :: "r"(a), "r"(parity) : "memory");
}

__global__ __launch_bounds__(NTHREADS, 5)
void wmse_tma_kernel(const float* __restrict__ x,
                     const int*   __restrict__ t,
                     const float* __restrict__ w,
                     float*       __restrict__ out)
{
    __shared__ alignas(128) float s_x[DEPTH][TILE_ELEMS];
    __shared__ alignas(128) int   s_t[DEPTH][TILE_ELEMS];
    __shared__ alignas(16)  unsigned long long s_mbar[DEPTH];
    __shared__ float  s_wrow[2][TILE_ROWS];    // double-buffered by tile parity
    __shared__ float  s_wtab[NUM_CLASSES];
    __shared__ float  s_rwd[NTHREADS / 32];
    __shared__ float  s_rpen[NTHREADS / 32];
    __shared__ bool   s_is_last;

    const unsigned tid = threadIdx.x;
    const unsigned b   = blockIdx.x;

    const unsigned nquads    = (b < BIG_BLOCKS) ? (QUADS_LO + 1u) : QUADS_LO;
    const unsigned startq    = QUADS_LO * b + min(b, BIG_BLOCKS);
    const unsigned rows      = nquads * 4u;
    const unsigned elem_base = startq * 84u;
    const unsigned ntiles    = (rows + TILE_ROWS - 1u) / TILE_ROWS;   // 43

    if (tid < NUM_CLASSES) s_wtab[tid] = w[tid];
    if (tid == 0) {
        #pragma unroll
        for (int i = 0; i < DEPTH; ++i)
            mbar_init(smem_u32(&s_mbar[i]), 1u);
    }
    __syncthreads();

    // Prime the pipeline (tiles 0..3)
    if (tid == 0) {
        #pragma unroll
        for (unsigned i = 0; i < DEPTH; ++i) {
            const unsigned trows = min(TILE_ROWS, rows - i * TILE_ROWS);
            const unsigned bytes = trows * F_COLS * 4u;
            const unsigned mb    = smem_u32(&s_mbar[i]);
            mbar_expect_tx(mb, 2u * bytes);
            bulk_g2s(smem_u32(&s_x[i][0]), x + elem_base + i * TILE_ELEMS, bytes, mb);
            bulk_g2s(smem_u32(&s_t[i][0]), t + elem_base + i * TILE_ELEMS, bytes, mb);
        }
    }

    // Per-thread slot constants: tile length ≡ 0 (mod 21) -> phases fixed across tiles.
    const unsigned e0 = tid * 4u;
    const unsigned e1 = (tid + NTHREADS) * 4u;
    const unsigned r0 = e0 / F_COLS,       r1 = e1 / F_COLS;
    const unsigned c0 = e0 - r0 * F_COLS,  c1 = e1 - r1 * F_COLS;
    const bool     bd0 = (c0 >= 18u),      bd1 = (c1 >= 18u);
    const unsigned sp0 = F_COLS - c0,      sp1 = F_COLS - c1;

    float accw = 0.0f, accp = 0.0f;

    for (unsigned i = 0; i < ntiles; ++i) {
        const unsigned stg = i & (DEPTH - 1u);
        const unsigned buf = i & 1u;
        mbar_wait(smem_u32(&s_mbar[stg]), (i >> 2) & 1u);

        const unsigned trows = min(TILE_ROWS, rows - i * TILE_ROWS);
        // Per-row work straight from smem (acquire on mbar wait makes it visible):
        // weight table into this tile's parity buffer + penalty once per row.
        if (tid < trows) {
            const int cls = s_t[stg][tid * F_COLS + 2u];
            s_wrow[buf][tid] = s_wtab[(unsigned)cls / 100u - 1u];
            const float vv = (float)s_t[stg][tid * F_COLS + 1u];
            if (vv > 1000.0f) {
                const float e = vv - 1000.0f;
                accp = fmaf(e, e, accp);
            } else if (vv < 0.0f) {
                accp = fmaf(vv, vv, accp);
            }
        }

        // Single barrier: (a) wrow[buf] for tile i is ready;
        // (b) every thread has fully consumed tile i-1's stage -> safe to refill it.
        __syncthreads();

        if (tid == 0 && i >= 1u) {
            const unsigned nx = i + DEPTH - 1u;          // = (i-1) + DEPTH
            if (nx < ntiles) {
                const unsigned rstg  = nx & (DEPTH - 1u); // == (i-1) & 3
                const unsigned trN   = min(TILE_ROWS, rows - nx * TILE_ROWS);
                const unsigned bytes = trN * F_COLS * 4u;
                const unsigned mb    = smem_u32(&s_mbar[rstg]);
                mbar_expect_tx(mb, 2u * bytes);
                bulk_g2s(smem_u32(&s_x[rstg][0]), x + elem_base + nx * TILE_ELEMS, bytes, mb);
                bulk_g2s(smem_u32(&s_t[rstg][0]), t + elem_base + nx * TILE_ELEMS, bytes, mb);
            }
        }

        const unsigned nvec = trows * F_COLS / 4u;   // trows multiple of 4 -> exact

        if (tid < nvec) {
            const float4 xv = *reinterpret_cast<const float4*>(&s_x[stg][e0]);
            const int4   tv = *reinterpret_cast<const int4*>(&s_t[stg][e0]);
            const float w0 = s_wrow[buf][r0];
            const float d0 = xv.x - (float)tv.x;
            const float d1 = xv.y - (float)tv.y;
            const float d2 = xv.z - (float)tv.z;
            const float d3 = xv.w - (float)tv.w;
            const float q0 = d0*d0, q1 = d1*d1, q2 = d2*d2, q3 = d3*d3;
            const float q  = (q0 + q1) + (q2 + q3);
            accw = fmaf(w0, q, accw);
            if (bd0) {
                const float w1 = s_wrow[buf][r0 + 1u];
                float qhi = q3;
                if (sp0 <= 2u) qhi += q2;
                if (sp0 <= 1u) qhi += q1;
                accw = fmaf(w1 - w0, qhi, accw);
            }
        }
        if (tid + NTHREADS < nvec) {
            const float4 xv = *reinterpret_cast<const float4*>(&s_x[stg][e1]);
            const int4   tv = *reinterpret_cast<const int4*>(&s_t[stg][e1]);
            const float w0 = s_wrow[buf][r1];
            const float d0 = xv.x - (float)tv.x;
            const float d1 = xv.y - (float)tv.y;
            const float d2 = xv.z - (float)tv.z;
            const float d3 = xv.w - (float)tv.w;
            const float q0 = d0*d0, q1 = d1*d1, q2 = d2*d2, q3 = d3*d3;
            const float q  = (q0 + q1) + (q2 + q3);
            accw = fmaf(w0, q, accw);
            if (bd1) {
                const float w1 = s_wrow[buf][r1 + 1u];
                float qhi = q3;
                if (sp1 <= 2u) qhi += q2;
                if (sp1 <= 1u) qhi += q1;
                accw = fmaf(w1 - w0, qhi, accw);
            }
        }
        // No trailing barrier: next iteration's single sync covers stage reuse.
    }

    // ---- block reduction ----
    #pragma unroll
    for (int o = 16; o > 0; o >>= 1) {
        accw += __shfl_xor_sync(0xffffffffu, accw, o);
        accp += __shfl_xor_sync(0xffffffffu, accp, o);
    }
    const int warp = tid >> 5;
    const int lane = tid & 31;
    if (lane == 0) { s_rwd[warp] = accw; s_rpen[warp] = accp; }
    __syncthreads();

    if (tid == 0) {
        double dw = 0.0, dp = 0.0;
        #pragma unroll
        for (int i = 0; i < NTHREADS / 32; ++i) { dw += (double)s_rwd[i]; dp += (double)s_rpen[i]; }
        g_part_wd[b]  = dw;
        g_part_pen[b] = dp;
        __threadfence();
        const unsigned prev = atomicAdd(&g_done_count, 1u);
        s_is_last = (prev == (unsigned)(gridDim.x - 1));
    }
    __syncthreads();

    if (s_is_last) {
        __threadfence();
        double dw = 0.0, dp = 0.0;
        for (unsigned i = tid; i < NBLOCKS; i += NTHREADS) {
            dw += g_part_wd[i];
            dp += g_part_pen[i];
        }
        #pragma unroll
        for (int o = 16; o > 0; o >>= 1) {
            dw += __shfl_xor_sync(0xffffffffu, dw, o);
            dp += __shfl_xor_sync(0xffffffffu, dp, o);
        }
        __shared__ double f_wd[NTHREADS / 32];
        __shared__ double f_pen[NTHREADS / 32];
        if (lane == 0) { f_wd[warp] = dw; f_pen[warp] = dp; }
        __syncthreads();
        if (tid == 0) {
            double tw = 0.0, tp = 0.0;
            #pragma unroll
            for (int i = 0; i < NTHREADS / 32; ++i) { tw += f_wd[i]; tp += f_pen[i]; }
            const double mean_wd = tw / (double)((unsigned long long)B_ROWS * F_COLS);
            out[0] = (float)(mean_wd + tp);
            g_done_count = 0;   // reset for next graph replay
        }
    }
}

extern "C" void kernel_launch(void* const* d_in, const int* in_sizes, int n_in,
                              void* d_out, int out_size)
{
    const float* x = nullptr;
    const int*   t = nullptr;
    const float* w = nullptr;
    int big_seen = 0;
    for (int i = 0; i < n_in; ++i) {
        if (in_sizes[i] == NUM_CLASSES) {
            w = (const float*)d_in[i];
        } else {
            if (big_seen == 0) x = (const float*)d_in[i];
            else               t = (const int*)d_in[i];
            big_seen++;
        }
    }
    wmse_tma_kernel<<<NBLOCKS, NTHREADS>>>(x, t, w, (float*)d_out);
}